// round 6
// baseline (speedup 1.0000x reference)
#include <cuda_runtime.h>
#include <cuda_fp16.h>
#include <cstdint>

#define NN   50000
#define EE   1600000
#define KP   25
#define KG   5
#define FOUT 64
#define KROW (KP * FOUT)          // 1600
#define PADR 72                   // row pad (half elems): 144B rows, LDSM conflict-free

// ---------------- device scratch (no runtime allocation allowed) -----------
__device__ __half g_xh[(size_t)NN * 64];         // fp16 x
__device__ __half g_wt[KP * 64 * 64];            // fp16 W^T: [k][o][i]
__device__ __half g_xw[(size_t)NN * KROW];       // 160 MB fp16 table
__device__ float  g_deg[NN];
__device__ int    g_cnt[NN];
__device__ int    g_off[NN];
__device__ uint4  g_erec[EE];                    // 25.6 MB edge records (col-sorted)

// ---------------- helpers ---------------------------------------------------
__device__ __forceinline__ uint32_t smem_u32(const void* p) {
    uint32_t a;
    asm("{ .reg .u64 t; cvta.to.shared.u64 t, %1; cvt.u32.u64 %0, t; }"
        : "=r"(a) : "l"(p));
    return a;
}
__device__ __forceinline__ void ldsm_x4(uint32_t addr, uint32_t* r) {
    asm volatile("ldmatrix.sync.aligned.m8n8.x4.shared.b16 {%0,%1,%2,%3}, [%4];"
                 : "=r"(r[0]), "=r"(r[1]), "=r"(r[2]), "=r"(r[3]) : "r"(addr));
}
__device__ __forceinline__ void mma_f16(float* c, const uint32_t* a, const uint32_t* b) {
    asm volatile(
        "mma.sync.aligned.m16n8k16.row.col.f32.f16.f16.f32 "
        "{%0,%1,%2,%3}, {%4,%5,%6,%7}, {%8,%9}, {%0,%1,%2,%3};"
        : "+f"(c[0]), "+f"(c[1]), "+f"(c[2]), "+f"(c[3])
        : "r"(a[0]), "r"(a[1]), "r"(a[2]), "r"(a[3]), "r"(b[0]), "r"(b[1]));
}

// ---------------------------------------------------------------------------
// prep kernels
// ---------------------------------------------------------------------------
__global__ void prep_x(const float* __restrict__ x, float* __restrict__ out) {
    int i = blockIdx.x * blockDim.x + threadIdx.x;
    if (i >= NN * 64) return;
    g_xh[i] = __float2half(x[i]);
    out[i] = 0.0f;
    if (i < NN) { g_deg[i] = 0.0f; g_cnt[i] = 0; }
}
__global__ void prep_w(const float* __restrict__ w) {
    int i = blockIdx.x * blockDim.x + threadIdx.x;
    if (i >= KP * 64 * 64) return;
    int k = i >> 12, rem = i & 4095;
    int ii = rem >> 6, o = rem & 63;
    g_wt[(k << 12) + (o << 6) + ii] = __float2half(w[i]);   // [k][o][i]
}
__global__ __launch_bounds__(256) void hist_kernel(const int* __restrict__ ei) {
    int e = blockIdx.x * blockDim.x + threadIdx.x;
    if (e < EE) atomicAdd(&g_cnt[ei[EE + e]], 1);
}
// single-block exclusive scan of g_cnt -> g_off
__global__ __launch_bounds__(1024) void scan_kernel() {
    __shared__ int s[1024];
    __shared__ int carry;
    int tid = threadIdx.x;
    if (tid == 0) carry = 0;
    __syncthreads();
    for (int base = 0; base < NN; base += 1024) {
        int idx = base + tid;
        int v = (idx < NN) ? g_cnt[idx] : 0;
        s[tid] = v;
        __syncthreads();
        #pragma unroll
        for (int off = 1; off < 1024; off <<= 1) {
            int t = (tid >= off) ? s[tid - off] : 0;
            __syncthreads();
            s[tid] += t;
            __syncthreads();
        }
        if (idx < NN) g_off[idx] = carry + s[tid] - v;
        __syncthreads();
        if (tid == 0) carry += s[1023];
        __syncthreads();
    }
}
// per-edge scalar math + col-sorted scatter of records + degree atomic
__global__ __launch_bounds__(256) void prep_edges(const int* __restrict__ ei,
                                                  const float* __restrict__ ps) {
    int e = blockIdx.x * blockDim.x + threadIdx.x;
    if (e >= EE) return;
    int row = ei[e];
    int col = ei[EE + e];
    float2 p = *(const float2*)(ps + 2 * e);
    float v0 = p.x * 4.0f, v1 = p.y * 4.0f;
    float fl0 = floorf(v0), fl1 = floorf(v1);
    float f0 = v0 - fl0, f1 = v1 - fl1;
    int i0 = (int)fl0, i1 = (int)fl1;            // 0..3, +1 in range (no wrap)
    unsigned c00 = (unsigned)(i0 * 5 + i1);
    unsigned cells = c00 | ((c00 + 5u) << 8) | ((c00 + 1u) << 16) | ((c00 + 6u) << 24);
    __half2 fh = __floats2half2_rn(f0, f1);
    uint4 rec;
    rec.x = (unsigned)(row * FOUT);
    rec.y = (unsigned)(col * KROW);
    rec.z = cells;
    rec.w = *(unsigned*)&fh;
    int slot = atomicAdd(&g_off[col], 1);
    g_erec[slot] = rec;
    atomicAdd(&g_deg[row], 1.0f);
}

// ---------------------------------------------------------------------------
// xw[n,k,:] = x[n,:] @ W[k] -- single-pass fp16 mma, staged coalesced epilogue
// 256 threads, 128 nodes x KG=5 slices. A fragments hoisted once.
// ---------------------------------------------------------------------------
__global__ __launch_bounds__(256) void xw_mma() {
    extern __shared__ __half sm[];
    __half* xs = sm;                   // [128][PADR]; reused as epilogue stage
    __half* ws = sm + 128 * PADR;      // [64][PADR]

    const int tid  = threadIdx.x;
    const int wid  = tid >> 5;
    const int lane = tid & 31;
    const int n0   = blockIdx.x * 128;

    // load x tile fp16 (128 rows x 64 half = 8 uint4/row)
    #pragma unroll
    for (int it = 0; it < 4; it++) {
        int flat = tid + 256 * it;
        int r = flat >> 3, j = flat & 7;
        int gn = n0 + r;
        uint4 v = make_uint4(0, 0, 0, 0);
        if (gn < NN) v = *(const uint4*)(g_xh + (size_t)gn * 64 + j * 8);
        *(uint4*)(xs + r * PADR + j * 8) = v;
    }
    __syncthreads();

    // hoist A fragments (16 rows/warp, K=64)
    const int m0    = wid * 16;
    const int a_row = m0 + (lane & 15);
    const int a_c8  = (lane >> 4) * 8;
    uint32_t ah[4][4];
    #pragma unroll
    for (int ks = 0; ks < 4; ks++)
        ldsm_x4(smem_u32(xs + a_row * PADR + ks * 16 + a_c8), ah[ks]);

    const int bw_r = lane & 7;
    const int bw_g = lane >> 3;
    const int g  = lane >> 2;
    const int t2 = (lane & 3) * 2;

    for (int j = 0; j < KG; j++) {
        const int k = blockIdx.y * KG + j;
        __syncthreads();   // stage copy of prev slice done; xs free; ws free
        // load W^T[k] (64 rows x 64 half)
        #pragma unroll
        for (int it = 0; it < 2; it++) {
            int flat = tid + 256 * it;
            int r = flat >> 3, jc = flat & 7;
            *(uint4*)(ws + r * PADR + jc * 8) =
                *(const uint4*)(g_wt + (k << 12) + r * 64 + jc * 8);
        }
        __syncthreads();

        #pragma unroll
        for (int nt = 0; nt < 8; nt++) {
            float acc[4] = {0.f, 0.f, 0.f, 0.f};
            uint32_t bh[8];
            uint32_t row_off = (nt * 8 + bw_r) * PADR + bw_g * 8;
            ldsm_x4(smem_u32(ws + row_off), bh);
            ldsm_x4(smem_u32(ws + row_off + 32), bh + 4);
            #pragma unroll
            for (int ks = 0; ks < 4; ks++)
                mma_f16(acc, ah[ks], bh + ks * 2);
            // stage results (conflict-free: bank = (36*relrow + t2/2) mod 32)
            __half2 h01 = __floats2half2_rn(acc[0], acc[1]);
            __half2 h23 = __floats2half2_rn(acc[2], acc[3]);
            *(__half2*)(xs + (m0 + g) * PADR + nt * 8 + t2)     = h01;
            *(__half2*)(xs + (m0 + g + 8) * PADR + nt * 8 + t2) = h23;
        }
        __syncthreads();
        // coalesced copy-out: 128 rows x 128B
        #pragma unroll
        for (int it = 0; it < 4; it++) {
            int flat = tid + 256 * it;
            int r = flat >> 3, jc = flat & 7;
            int gn = n0 + r;
            if (gn < NN)
                *(uint4*)(g_xw + (size_t)gn * KROW + k * 64 + jc * 8) =
                    *(const uint4*)(xs + r * PADR + jc * 8);
        }
    }
}

// ---------------------------------------------------------------------------
// edge pass: record-driven (col-sorted). 2 edges per warp-iteration.
// ---------------------------------------------------------------------------
__global__ __launch_bounds__(256) void edge_kernel(float* __restrict__ out) {
    const int warp   = (blockIdx.x * blockDim.x + threadIdx.x) >> 5;
    const int lane2  = (threadIdx.x & 31) * 2;
    const int nwarps = (gridDim.x * blockDim.x) >> 5;

    for (int e = warp * 2; e < EE; e += nwarps * 2) {
        uint4 r0 = g_erec[e];
        uint4 r1 = g_erec[e + 1];

        const __half* p0 = g_xw + r0.y + lane2;
        const __half* p1 = g_xw + r1.y + lane2;
        unsigned c0 = r0.z, c1 = r1.z;

        __half2 A0 = *(const __half2*)(p0 + ((c0 & 255u) << 6));
        __half2 B0 = *(const __half2*)(p0 + (((c0 >> 8) & 255u) << 6));
        __half2 C0 = *(const __half2*)(p0 + (((c0 >> 16) & 255u) << 6));
        __half2 D0 = *(const __half2*)(p0 + ((c0 >> 24) << 6));
        __half2 A1 = *(const __half2*)(p1 + ((c1 & 255u) << 6));
        __half2 B1 = *(const __half2*)(p1 + (((c1 >> 8) & 255u) << 6));
        __half2 C1 = *(const __half2*)(p1 + (((c1 >> 16) & 255u) << 6));
        __half2 D1 = *(const __half2*)(p1 + ((c1 >> 24) << 6));

        {
            float2 f = __half22float2(*(const __half2*)&r0.w);
            float g0 = 1.0f - f.x, g1 = 1.0f - f.y;
            float w00 = g0 * g1, w10 = f.x * g1, w01 = g0 * f.y, w11 = f.x * f.y;
            float2 a = __half22float2(A0), b = __half22float2(B0);
            float2 c = __half22float2(C0), d = __half22float2(D0);
            float rx = w00 * a.x + w10 * b.x + w01 * c.x + w11 * d.x;
            float ry = w00 * a.y + w10 * b.y + w01 * c.y + w11 * d.y;
            float* op = out + r0.x + lane2;
            asm volatile("red.global.add.v2.f32 [%0], {%1, %2};"
                         :: "l"(op), "f"(rx), "f"(ry) : "memory");
        }
        {
            float2 f = __half22float2(*(const __half2*)&r1.w);
            float g0 = 1.0f - f.x, g1 = 1.0f - f.y;
            float w00 = g0 * g1, w10 = f.x * g1, w01 = g0 * f.y, w11 = f.x * f.y;
            float2 a = __half22float2(A1), b = __half22float2(B1);
            float2 c = __half22float2(C1), d = __half22float2(D1);
            float sx = w00 * a.x + w10 * b.x + w01 * c.x + w11 * d.x;
            float sy = w00 * a.y + w10 * b.y + w01 * c.y + w11 * d.y;
            float* op = out + r1.x + lane2;
            asm volatile("red.global.add.v2.f32 [%0], {%1, %2};"
                         :: "l"(op), "f"(sx), "f"(sy) : "memory");
        }
    }
}

// ---------------------------------------------------------------------------
// final: out = out / max(deg,1) + x @ root + bias
// ---------------------------------------------------------------------------
__global__ __launch_bounds__(256) void final_kernel(const float* __restrict__ x,
                                                    const float* __restrict__ root,
                                                    const float* __restrict__ bias,
                                                    float*       __restrict__ out) {
    __shared__ float As[64][128];
    __shared__ float Rs[64][64];
    const int n0  = blockIdx.x * 128;
    const int tid = threadIdx.x;

    {
        const float4* src = (const float4*)root;
        float4* dst = (float4*)(&Rs[0][0]);
        #pragma unroll
        for (int j = 0; j < 4; j++) dst[j * 256 + tid] = src[j * 256 + tid];
    }
    #pragma unroll
    for (int it = 0; it < 8; it++) {
        int flat = it * 256 + tid;
        int n  = flat & 127;
        int i4 = flat >> 7;
        float4 v = make_float4(0.f, 0.f, 0.f, 0.f);
        int gn = n0 + n;
        if (gn < NN) v = *(const float4*)(x + (size_t)gn * 64 + i4 * 4);
        As[i4 * 4 + 0][n] = v.x;
        As[i4 * 4 + 1][n] = v.y;
        As[i4 * 4 + 2][n] = v.z;
        As[i4 * 4 + 3][n] = v.w;
    }
    __syncthreads();

    const int tx = tid & 7;
    const int ty = tid >> 3;
    float acc[4][8];
    #pragma unroll
    for (int m = 0; m < 4; m++)
        #pragma unroll
        for (int o = 0; o < 8; o++) acc[m][o] = 0.f;

    #pragma unroll 8
    for (int kk = 0; kk < 64; kk++) {
        float4 a  = *(const float4*)(&As[kk][ty * 4]);
        float4 b0 = *(const float4*)(&Rs[kk][tx * 8]);
        float4 b1 = *(const float4*)(&Rs[kk][tx * 8 + 4]);
        float av[4] = {a.x, a.y, a.z, a.w};
        float bv[8] = {b0.x, b0.y, b0.z, b0.w, b1.x, b1.y, b1.z, b1.w};
        #pragma unroll
        for (int m = 0; m < 4; m++)
            #pragma unroll
            for (int o = 0; o < 8; o++)
                acc[m][o] = fmaf(av[m], bv[o], acc[m][o]);
    }

    #pragma unroll
    for (int m = 0; m < 4; m++) {
        int gn = n0 + ty * 4 + m;
        if (gn < NN) {
            float scale = 1.0f / fmaxf(g_deg[gn], 1.0f);
            float* dst = out + (size_t)gn * 64 + tx * 8;
            #pragma unroll
            for (int o = 0; o < 8; o++) {
                dst[o] = dst[o] * scale + acc[m][o] + __ldg(bias + tx * 8 + o);
            }
        }
    }
}

// ---------------------------------------------------------------------------
extern "C" void kernel_launch(void* const* d_in, const int* in_sizes, int n_in,
                              void* d_out, int out_size) {
    const float* x      = (const float*)d_in[0];
    const int*   ei     = (const int*)  d_in[1];
    const float* pseudo = (const float*)d_in[2];
    const float* weight = (const float*)d_in[3];
    const float* root   = (const float*)d_in[4];
    const float* bias   = (const float*)d_in[5];
    float* out = (float*)d_out;

    const int smem_bytes = (128 * PADR + 64 * PADR) * (int)sizeof(__half);
    cudaFuncSetAttribute(xw_mma, cudaFuncAttributeMaxDynamicSharedMemorySize, smem_bytes);

    prep_x<<<(NN * 64 + 255) / 256, 256>>>(x, out);
    prep_w<<<(KP * 64 * 64 + 255) / 256, 256>>>(weight);
    hist_kernel<<<(EE + 255) / 256, 256>>>(ei);
    scan_kernel<<<1, 1024>>>();
    prep_edges<<<(EE + 255) / 256, 256>>>(ei, pseudo);

    dim3 g2((NN + 127) / 128, KP / KG);
    xw_mma<<<g2, 256, smem_bytes>>>();

    edge_kernel<<<6144, 256>>>(out);

    final_kernel<<<(NN + 127) / 128, 256>>>(x, root, bias, out);
}

// round 7
// speedup vs baseline: 1.2439x; 1.2439x over previous
#include <cuda_runtime.h>
#include <cuda_fp16.h>
#include <cstdint>

#define NN   50000
#define EE   1600000
#define KP   25
#define KG   5
#define FOUT 64
#define KROW (KP * FOUT)          // 1600
#define PADR 72                   // row pad (half elems): 144B rows, LDSM conflict-free
#define NBLK ((NN + 1023) / 1024) // 49 scan blocks

// ---------------- device scratch (no runtime allocation allowed) -----------
__device__ __half g_xh[(size_t)NN * 64];         // fp16 x
__device__ __half g_wt[KP * 64 * 64];            // fp16 W^T: [k][o][i]
__device__ __half g_xw[(size_t)NN * KROW];       // 160 MB fp16 table
__device__ float  g_deg[NN];
__device__ int    g_cnt[NN];
__device__ int    g_off[NN];
__device__ int    g_bsum[NBLK];
__device__ uint4  g_erec[EE];                    // 25.6 MB edge records (col-sorted)

// ---------------- helpers ---------------------------------------------------
__device__ __forceinline__ uint32_t smem_u32(const void* p) {
    uint32_t a;
    asm("{ .reg .u64 t; cvta.to.shared.u64 t, %1; cvt.u32.u64 %0, t; }"
        : "=r"(a) : "l"(p));
    return a;
}
__device__ __forceinline__ void ldsm_x4(uint32_t addr, uint32_t* r) {
    asm volatile("ldmatrix.sync.aligned.m8n8.x4.shared.b16 {%0,%1,%2,%3}, [%4];"
                 : "=r"(r[0]), "=r"(r[1]), "=r"(r[2]), "=r"(r[3]) : "r"(addr));
}
__device__ __forceinline__ void mma_f16(float* c, const uint32_t* a, const uint32_t* b) {
    asm volatile(
        "mma.sync.aligned.m16n8k16.row.col.f32.f16.f16.f32 "
        "{%0,%1,%2,%3}, {%4,%5,%6,%7}, {%8,%9}, {%0,%1,%2,%3};"
        : "+f"(c[0]), "+f"(c[1]), "+f"(c[2]), "+f"(c[3])
        : "r"(a[0]), "r"(a[1]), "r"(a[2]), "r"(a[3]), "r"(b[0]), "r"(b[1]));
}

// ---------------------------------------------------------------------------
// prep kernels
// ---------------------------------------------------------------------------
__global__ void prep_x(const float* __restrict__ x, float* __restrict__ out) {
    int i = blockIdx.x * blockDim.x + threadIdx.x;
    if (i >= NN * 64) return;
    g_xh[i] = __float2half(x[i]);
    out[i] = 0.0f;
    if (i < NN) { g_deg[i] = 0.0f; g_cnt[i] = 0; }
}
__global__ void prep_w(const float* __restrict__ w) {
    int i = blockIdx.x * blockDim.x + threadIdx.x;
    if (i >= KP * 64 * 64) return;
    int k = i >> 12, rem = i & 4095;
    int ii = rem >> 6, o = rem & 63;
    g_wt[(k << 12) + (o << 6) + ii] = __float2half(w[i]);   // [k][o][i]
}
__global__ __launch_bounds__(256) void hist_kernel(const int* __restrict__ ei) {
    int e = blockIdx.x * blockDim.x + threadIdx.x;
    if (e < EE) atomicAdd(&g_cnt[ei[EE + e]], 1);
}
// ---- 3-pass device scan: local shuffle scan -> tops scan -> uniform add ----
__global__ __launch_bounds__(1024) void scan_local() {
    __shared__ int wsum[32];
    int idx  = blockIdx.x * 1024 + threadIdx.x;
    int lane = threadIdx.x & 31;
    int wid  = threadIdx.x >> 5;
    int v = (idx < NN) ? g_cnt[idx] : 0;
    int s = v;
    #pragma unroll
    for (int o = 1; o < 32; o <<= 1) {
        int t = __shfl_up_sync(0xFFFFFFFFu, s, o);
        if (lane >= o) s += t;
    }
    if (lane == 31) wsum[wid] = s;
    __syncthreads();
    if (wid == 0) {
        int ws = wsum[lane];
        #pragma unroll
        for (int o = 1; o < 32; o <<= 1) {
            int t = __shfl_up_sync(0xFFFFFFFFu, ws, o);
            if (lane >= o) ws += t;
        }
        wsum[lane] = ws;
    }
    __syncthreads();
    int excl = s - v + (wid > 0 ? wsum[wid - 1] : 0);
    if (idx < NN) g_off[idx] = excl;
    if (threadIdx.x == 1023) g_bsum[blockIdx.x] = excl + v;
}
__global__ __launch_bounds__(64) void scan_tops() {
    __shared__ int s[64];
    int tid = threadIdx.x;
    s[tid] = (tid < NBLK) ? g_bsum[tid] : 0;
    __syncthreads();
    if (tid == 0) {
        int acc = 0;
        #pragma unroll 1
        for (int i = 0; i < NBLK; i++) { int t = s[i]; s[i] = acc; acc += t; }
    }
    __syncthreads();
    if (tid < NBLK) g_bsum[tid] = s[tid];
}
__global__ __launch_bounds__(1024) void scan_add() {
    int idx = blockIdx.x * 1024 + threadIdx.x;
    if (idx < NN) g_off[idx] += g_bsum[blockIdx.x];
}
// per-edge scalar math + col-sorted scatter of records + degree atomic
__global__ __launch_bounds__(256) void prep_edges(const int* __restrict__ ei,
                                                  const float* __restrict__ ps) {
    int e = blockIdx.x * blockDim.x + threadIdx.x;
    if (e >= EE) return;
    int row = ei[e];
    int col = ei[EE + e];
    float2 p = *(const float2*)(ps + 2 * e);
    float v0 = p.x * 4.0f, v1 = p.y * 4.0f;
    float fl0 = floorf(v0), fl1 = floorf(v1);
    float f0 = v0 - fl0, f1 = v1 - fl1;
    int i0 = (int)fl0, i1 = (int)fl1;            // 0..3, +1 in range (no wrap)
    unsigned c00 = (unsigned)(i0 * 5 + i1);
    unsigned cells = c00 | ((c00 + 5u) << 8) | ((c00 + 1u) << 16) | ((c00 + 6u) << 24);
    __half2 fh = __floats2half2_rn(f0, f1);
    uint4 rec;
    rec.x = (unsigned)(row * FOUT);
    rec.y = (unsigned)(col * KROW);
    rec.z = cells;
    rec.w = *(unsigned*)&fh;
    int slot = atomicAdd(&g_off[col], 1);
    g_erec[slot] = rec;
    atomicAdd(&g_deg[row], 1.0f);
}

// ---------------------------------------------------------------------------
// xw[n,k,:] = x[n,:] @ W[k] -- single-pass fp16 mma, staged coalesced epilogue
// ---------------------------------------------------------------------------
__global__ __launch_bounds__(256) void xw_mma() {
    extern __shared__ __half sm[];
    __half* xs = sm;                   // [128][PADR]; reused as epilogue stage
    __half* ws = sm + 128 * PADR;      // [64][PADR]

    const int tid  = threadIdx.x;
    const int wid  = tid >> 5;
    const int lane = tid & 31;
    const int n0   = blockIdx.x * 128;

    #pragma unroll
    for (int it = 0; it < 4; it++) {
        int flat = tid + 256 * it;
        int r = flat >> 3, j = flat & 7;
        int gn = n0 + r;
        uint4 v = make_uint4(0, 0, 0, 0);
        if (gn < NN) v = *(const uint4*)(g_xh + (size_t)gn * 64 + j * 8);
        *(uint4*)(xs + r * PADR + j * 8) = v;
    }
    __syncthreads();

    const int m0    = wid * 16;
    const int a_row = m0 + (lane & 15);
    const int a_c8  = (lane >> 4) * 8;
    uint32_t ah[4][4];
    #pragma unroll
    for (int ks = 0; ks < 4; ks++)
        ldsm_x4(smem_u32(xs + a_row * PADR + ks * 16 + a_c8), ah[ks]);

    const int bw_r = lane & 7;
    const int bw_g = lane >> 3;
    const int g  = lane >> 2;
    const int t2 = (lane & 3) * 2;

    for (int j = 0; j < KG; j++) {
        const int k = blockIdx.y * KG + j;
        __syncthreads();
        #pragma unroll
        for (int it = 0; it < 2; it++) {
            int flat = tid + 256 * it;
            int r = flat >> 3, jc = flat & 7;
            *(uint4*)(ws + r * PADR + jc * 8) =
                *(const uint4*)(g_wt + (k << 12) + r * 64 + jc * 8);
        }
        __syncthreads();

        #pragma unroll
        for (int nt = 0; nt < 8; nt++) {
            float acc[4] = {0.f, 0.f, 0.f, 0.f};
            uint32_t bh[8];
            uint32_t row_off = (nt * 8 + bw_r) * PADR + bw_g * 8;
            ldsm_x4(smem_u32(ws + row_off), bh);
            ldsm_x4(smem_u32(ws + row_off + 32), bh + 4);
            #pragma unroll
            for (int ks = 0; ks < 4; ks++)
                mma_f16(acc, ah[ks], bh + ks * 2);
            __half2 h01 = __floats2half2_rn(acc[0], acc[1]);
            __half2 h23 = __floats2half2_rn(acc[2], acc[3]);
            *(__half2*)(xs + (m0 + g) * PADR + nt * 8 + t2)     = h01;
            *(__half2*)(xs + (m0 + g + 8) * PADR + nt * 8 + t2) = h23;
        }
        __syncthreads();
        #pragma unroll
        for (int it = 0; it < 4; it++) {
            int flat = tid + 256 * it;
            int r = flat >> 3, jc = flat & 7;
            int gn = n0 + r;
            if (gn < NN)
                *(uint4*)(g_xw + (size_t)gn * KROW + k * 64 + jc * 8) =
                    *(const uint4*)(xs + r * PADR + jc * 8);
        }
    }
}

// ---------------------------------------------------------------------------
// edge pass: record-driven (col-sorted). 2 edges per warp-iteration.
// ---------------------------------------------------------------------------
__global__ __launch_bounds__(256) void edge_kernel(float* __restrict__ out) {
    const int warp   = (blockIdx.x * blockDim.x + threadIdx.x) >> 5;
    const int lane2  = (threadIdx.x & 31) * 2;
    const int nwarps = (gridDim.x * blockDim.x) >> 5;

    for (int e = warp * 2; e < EE; e += nwarps * 2) {
        uint4 r0 = g_erec[e];
        uint4 r1 = g_erec[e + 1];

        const __half* p0 = g_xw + r0.y + lane2;
        const __half* p1 = g_xw + r1.y + lane2;
        unsigned c0 = r0.z, c1 = r1.z;

        __half2 A0 = *(const __half2*)(p0 + ((c0 & 255u) << 6));
        __half2 B0 = *(const __half2*)(p0 + (((c0 >> 8) & 255u) << 6));
        __half2 C0 = *(const __half2*)(p0 + (((c0 >> 16) & 255u) << 6));
        __half2 D0 = *(const __half2*)(p0 + ((c0 >> 24) << 6));
        __half2 A1 = *(const __half2*)(p1 + ((c1 & 255u) << 6));
        __half2 B1 = *(const __half2*)(p1 + (((c1 >> 8) & 255u) << 6));
        __half2 C1 = *(const __half2*)(p1 + (((c1 >> 16) & 255u) << 6));
        __half2 D1 = *(const __half2*)(p1 + ((c1 >> 24) << 6));

        {
            float2 f = __half22float2(*(const __half2*)&r0.w);
            float g0 = 1.0f - f.x, g1 = 1.0f - f.y;
            float w00 = g0 * g1, w10 = f.x * g1, w01 = g0 * f.y, w11 = f.x * f.y;
            float2 a = __half22float2(A0), b = __half22float2(B0);
            float2 c = __half22float2(C0), d = __half22float2(D0);
            float rx = w00 * a.x + w10 * b.x + w01 * c.x + w11 * d.x;
            float ry = w00 * a.y + w10 * b.y + w01 * c.y + w11 * d.y;
            float* op = out + r0.x + lane2;
            asm volatile("red.global.add.v2.f32 [%0], {%1, %2};"
                         :: "l"(op), "f"(rx), "f"(ry) : "memory");
        }
        {
            float2 f = __half22float2(*(const __half2*)&r1.w);
            float g0 = 1.0f - f.x, g1 = 1.0f - f.y;
            float w00 = g0 * g1, w10 = f.x * g1, w01 = g0 * f.y, w11 = f.x * f.y;
            float2 a = __half22float2(A1), b = __half22float2(B1);
            float2 c = __half22float2(C1), d = __half22float2(D1);
            float sx = w00 * a.x + w10 * b.x + w01 * c.x + w11 * d.x;
            float sy = w00 * a.y + w10 * b.y + w01 * c.y + w11 * d.y;
            float* op = out + r1.x + lane2;
            asm volatile("red.global.add.v2.f32 [%0], {%1, %2};"
                         :: "l"(op), "f"(sx), "f"(sy) : "memory");
        }
    }
}

// ---------------------------------------------------------------------------
// final: out = out / max(deg,1) + x @ root + bias
// ---------------------------------------------------------------------------
__global__ __launch_bounds__(256) void final_kernel(const float* __restrict__ x,
                                                    const float* __restrict__ root,
                                                    const float* __restrict__ bias,
                                                    float*       __restrict__ out) {
    __shared__ float As[64][128];
    __shared__ float Rs[64][64];
    const int n0  = blockIdx.x * 128;
    const int tid = threadIdx.x;

    {
        const float4* src = (const float4*)root;
        float4* dst = (float4*)(&Rs[0][0]);
        #pragma unroll
        for (int j = 0; j < 4; j++) dst[j * 256 + tid] = src[j * 256 + tid];
    }
    #pragma unroll
    for (int it = 0; it < 8; it++) {
        int flat = it * 256 + tid;
        int n  = flat & 127;
        int i4 = flat >> 7;
        float4 v = make_float4(0.f, 0.f, 0.f, 0.f);
        int gn = n0 + n;
        if (gn < NN) v = *(const float4*)(x + (size_t)gn * 64 + i4 * 4);
        As[i4 * 4 + 0][n] = v.x;
        As[i4 * 4 + 1][n] = v.y;
        As[i4 * 4 + 2][n] = v.z;
        As[i4 * 4 + 3][n] = v.w;
    }
    __syncthreads();

    const int tx = tid & 7;
    const int ty = tid >> 3;
    float acc[4][8];
    #pragma unroll
    for (int m = 0; m < 4; m++)
        #pragma unroll
        for (int o = 0; o < 8; o++) acc[m][o] = 0.f;

    #pragma unroll 8
    for (int kk = 0; kk < 64; kk++) {
        float4 a  = *(const float4*)(&As[kk][ty * 4]);
        float4 b0 = *(const float4*)(&Rs[kk][tx * 8]);
        float4 b1 = *(const float4*)(&Rs[kk][tx * 8 + 4]);
        float av[4] = {a.x, a.y, a.z, a.w};
        float bv[8] = {b0.x, b0.y, b0.z, b0.w, b1.x, b1.y, b1.z, b1.w};
        #pragma unroll
        for (int m = 0; m < 4; m++)
            #pragma unroll
            for (int o = 0; o < 8; o++)
                acc[m][o] = fmaf(av[m], bv[o], acc[m][o]);
    }

    #pragma unroll
    for (int m = 0; m < 4; m++) {
        int gn = n0 + ty * 4 + m;
        if (gn < NN) {
            float scale = 1.0f / fmaxf(g_deg[gn], 1.0f);
            float* dst = out + (size_t)gn * 64 + tx * 8;
            #pragma unroll
            for (int o = 0; o < 8; o++) {
                dst[o] = dst[o] * scale + acc[m][o] + __ldg(bias + tx * 8 + o);
            }
        }
    }
}

// ---------------------------------------------------------------------------
extern "C" void kernel_launch(void* const* d_in, const int* in_sizes, int n_in,
                              void* d_out, int out_size) {
    const float* x      = (const float*)d_in[0];
    const int*   ei     = (const int*)  d_in[1];
    const float* pseudo = (const float*)d_in[2];
    const float* weight = (const float*)d_in[3];
    const float* root   = (const float*)d_in[4];
    const float* bias   = (const float*)d_in[5];
    float* out = (float*)d_out;

    const int smem_bytes = (128 * PADR + 64 * PADR) * (int)sizeof(__half);
    cudaFuncSetAttribute(xw_mma, cudaFuncAttributeMaxDynamicSharedMemorySize, smem_bytes);

    prep_x<<<(NN * 64 + 255) / 256, 256>>>(x, out);
    prep_w<<<(KP * 64 * 64 + 255) / 256, 256>>>(weight);
    hist_kernel<<<(EE + 255) / 256, 256>>>(ei);
    scan_local<<<NBLK, 1024>>>();
    scan_tops<<<1, 64>>>();
    scan_add<<<NBLK, 1024>>>();
    prep_edges<<<(EE + 255) / 256, 256>>>(ei, pseudo);

    dim3 g2((NN + 127) / 128, KP / KG);
    xw_mma<<<g2, 256, smem_bytes>>>();

    edge_kernel<<<6144, 256>>>(out);

    final_kernel<<<(NN + 127) / 128, 256>>>(x, root, bias, out);
}

// round 8
// speedup vs baseline: 1.3622x; 1.0951x over previous
#include <cuda_runtime.h>
#include <cuda_fp16.h>
#include <cstdint>

#define NN    50000
#define EE    1600000
#define KP    25
#define KALL  26                    // 25 spline mats + root
#define FOUT  64
#define KROW  (KALL * FOUT)         // 1664 halves per node row
#define PADR  72                    // row pad (half): 144B rows, LDSM conflict-free
#define NBLK  ((NN + 1023) / 1024)  // scan blocks

// ---------------- device scratch (no runtime allocation allowed) -----------
__device__ __half g_xh[(size_t)NN * 64];
__device__ __half g_wt[KALL * 64 * 64];          // fp16 W^T: [k][o][i], k=25 is root
__device__ __half g_xw[(size_t)NN * KROW];       // 166 MB fp16 table
__device__ float  g_deg[NN];
__device__ int    g_cnt[NN];
__device__ int    g_off[NN];
__device__ int    g_bsum[NBLK];
__device__ uint4  g_erec[EE];                    // edge records (col-sorted)

// ---------------- helpers ---------------------------------------------------
__device__ __forceinline__ uint32_t smem_u32(const void* p) {
    uint32_t a;
    asm("{ .reg .u64 t; cvta.to.shared.u64 t, %1; cvt.u32.u64 %0, t; }"
        : "=r"(a) : "l"(p));
    return a;
}
__device__ __forceinline__ void ldsm_x4(uint32_t addr, uint32_t* r) {
    asm volatile("ldmatrix.sync.aligned.m8n8.x4.shared.b16 {%0,%1,%2,%3}, [%4];"
                 : "=r"(r[0]), "=r"(r[1]), "=r"(r[2]), "=r"(r[3]) : "r"(addr));
}
__device__ __forceinline__ void mma_f16(float* c, const uint32_t* a, const uint32_t* b) {
    asm volatile(
        "mma.sync.aligned.m16n8k16.row.col.f32.f16.f16.f32 "
        "{%0,%1,%2,%3}, {%4,%5,%6,%7}, {%8,%9}, {%0,%1,%2,%3};"
        : "+f"(c[0]), "+f"(c[1]), "+f"(c[2]), "+f"(c[3])
        : "r"(a[0]), "r"(a[1]), "r"(a[2]), "r"(a[3]), "r"(b[0]), "r"(b[1]));
}

// ---------------------------------------------------------------------------
// prep kernels
// ---------------------------------------------------------------------------
__global__ void prep_x(const float* __restrict__ x, float* __restrict__ out) {
    int i = blockIdx.x * blockDim.x + threadIdx.x;
    if (i >= NN * 64) return;
    g_xh[i] = __float2half(x[i]);
    out[i] = 0.0f;
    if (i < NN) { g_deg[i] = 0.0f; g_cnt[i] = 0; }
}
__global__ void prep_w(const float* __restrict__ w, const float* __restrict__ root) {
    int i = blockIdx.x * blockDim.x + threadIdx.x;
    if (i >= KALL * 64 * 64) return;
    int k = i >> 12, rem = i & 4095;
    int ii = rem >> 6, o = rem & 63;
    float v = (k < KP) ? w[i] : root[rem];
    g_wt[(k << 12) + (o << 6) + ii] = __float2half(v);    // [k][o][i]
}
__global__ __launch_bounds__(256) void hist_kernel(const int* __restrict__ ei) {
    int e = blockIdx.x * blockDim.x + threadIdx.x;
    if (e < EE) atomicAdd(&g_cnt[ei[EE + e]], 1);
}
// ---- 3-pass device scan ----
__global__ __launch_bounds__(1024) void scan_local() {
    __shared__ int wsum[32];
    int idx  = blockIdx.x * 1024 + threadIdx.x;
    int lane = threadIdx.x & 31;
    int wid  = threadIdx.x >> 5;
    int v = (idx < NN) ? g_cnt[idx] : 0;
    int s = v;
    #pragma unroll
    for (int o = 1; o < 32; o <<= 1) {
        int t = __shfl_up_sync(0xFFFFFFFFu, s, o);
        if (lane >= o) s += t;
    }
    if (lane == 31) wsum[wid] = s;
    __syncthreads();
    if (wid == 0) {
        int ws = wsum[lane];
        #pragma unroll
        for (int o = 1; o < 32; o <<= 1) {
            int t = __shfl_up_sync(0xFFFFFFFFu, ws, o);
            if (lane >= o) ws += t;
        }
        wsum[lane] = ws;
    }
    __syncthreads();
    int excl = s - v + (wid > 0 ? wsum[wid - 1] : 0);
    if (idx < NN) g_off[idx] = excl;
    if (threadIdx.x == 1023) g_bsum[blockIdx.x] = excl + v;
}
__global__ __launch_bounds__(64) void scan_tops() {
    __shared__ int s[64];
    int tid = threadIdx.x;
    s[tid] = (tid < NBLK) ? g_bsum[tid] : 0;
    __syncthreads();
    if (tid == 0) {
        int acc = 0;
        #pragma unroll 1
        for (int i = 0; i < NBLK; i++) { int t = s[i]; s[i] = acc; acc += t; }
    }
    __syncthreads();
    if (tid < NBLK) g_bsum[tid] = s[tid];
}
__global__ __launch_bounds__(1024) void scan_add() {
    int idx = blockIdx.x * 1024 + threadIdx.x;
    if (idx < NN) g_off[idx] += g_bsum[blockIdx.x];
}
// per-edge scalar math + col-sorted record scatter + degree atomic
__global__ __launch_bounds__(256) void prep_edges(const int* __restrict__ ei,
                                                  const float* __restrict__ ps) {
    int e = blockIdx.x * blockDim.x + threadIdx.x;
    if (e >= EE) return;
    int row = ei[e];
    int col = ei[EE + e];
    float2 p = *(const float2*)(ps + 2 * e);
    float v0 = p.x * 4.0f, v1 = p.y * 4.0f;
    float fl0 = floorf(v0), fl1 = floorf(v1);
    float f0 = v0 - fl0, f1 = v1 - fl1;
    int i0 = (int)fl0, i1 = (int)fl1;            // 0..3, +1 in range
    unsigned c00 = (unsigned)(i0 * 5 + i1);
    unsigned cells = c00 | ((c00 + 5u) << 8) | ((c00 + 1u) << 16) | ((c00 + 6u) << 24);
    __half2 fh = __floats2half2_rn(f0, f1);
    uint4 rec;
    rec.x = (unsigned)(row * FOUT);
    rec.y = (unsigned)(col * KROW);
    rec.z = cells;
    rec.w = *(unsigned*)&fh;
    int slot = atomicAdd(&g_off[col], 1);
    g_erec[slot] = rec;
    atomicAdd(&g_deg[row], 1.0f);
}

// ---------------------------------------------------------------------------
// xw[n,k,:] = x[n,:] @ W[k], k=0..25 (25=root). Single-pass fp16 mma.
// grid.y: 0..4 -> 5 slices each; 5 -> 1 slice (k=25).
// ---------------------------------------------------------------------------
__global__ __launch_bounds__(256) void xw_mma() {
    extern __shared__ __half sm[];
    __half* xs = sm;                   // [128][PADR]; reused as epilogue stage
    __half* ws = sm + 128 * PADR;      // [64][PADR]

    const int tid  = threadIdx.x;
    const int wid  = tid >> 5;
    const int lane = tid & 31;
    const int n0   = blockIdx.x * 128;
    const int kbeg = blockIdx.y * 5;
    const int kcnt = (blockIdx.y == 5) ? 1 : 5;

    #pragma unroll
    for (int it = 0; it < 4; it++) {
        int flat = tid + 256 * it;
        int r = flat >> 3, j = flat & 7;
        int gn = n0 + r;
        uint4 v = make_uint4(0, 0, 0, 0);
        if (gn < NN) v = *(const uint4*)(g_xh + (size_t)gn * 64 + j * 8);
        *(uint4*)(xs + r * PADR + j * 8) = v;
    }
    __syncthreads();

    const int m0    = wid * 16;
    const int a_row = m0 + (lane & 15);
    const int a_c8  = (lane >> 4) * 8;
    uint32_t ah[4][4];
    #pragma unroll
    for (int ks = 0; ks < 4; ks++)
        ldsm_x4(smem_u32(xs + a_row * PADR + ks * 16 + a_c8), ah[ks]);

    const int bw_r = lane & 7;
    const int bw_g = lane >> 3;
    const int g  = lane >> 2;
    const int t2 = (lane & 3) * 2;

    for (int j = 0; j < kcnt; j++) {
        const int k = kbeg + j;
        __syncthreads();
        #pragma unroll
        for (int it = 0; it < 2; it++) {
            int flat = tid + 256 * it;
            int r = flat >> 3, jc = flat & 7;
            *(uint4*)(ws + r * PADR + jc * 8) =
                *(const uint4*)(g_wt + (k << 12) + r * 64 + jc * 8);
        }
        __syncthreads();

        #pragma unroll
        for (int nt = 0; nt < 8; nt++) {
            float acc[4] = {0.f, 0.f, 0.f, 0.f};
            uint32_t bh[8];
            uint32_t row_off = (nt * 8 + bw_r) * PADR + bw_g * 8;
            ldsm_x4(smem_u32(ws + row_off), bh);
            ldsm_x4(smem_u32(ws + row_off + 32), bh + 4);
            #pragma unroll
            for (int ks = 0; ks < 4; ks++)
                mma_f16(acc, ah[ks], bh + ks * 2);
            __half2 h01 = __floats2half2_rn(acc[0], acc[1]);
            __half2 h23 = __floats2half2_rn(acc[2], acc[3]);
            *(__half2*)(xs + (m0 + g) * PADR + nt * 8 + t2)     = h01;
            *(__half2*)(xs + (m0 + g + 8) * PADR + nt * 8 + t2) = h23;
        }
        __syncthreads();
        #pragma unroll
        for (int it = 0; it < 4; it++) {
            int flat = tid + 256 * it;
            int r = flat >> 3, jc = flat & 7;
            int gn = n0 + r;
            if (gn < NN)
                *(uint4*)(g_xw + (size_t)gn * KROW + k * 64 + jc * 8) =
                    *(const uint4*)(xs + r * PADR + jc * 8);
        }
    }
}

// ---------------------------------------------------------------------------
// edge pass: half-warp per edge; 16 lanes x 4 halves; fp16 blend; red.v4.f32
// ---------------------------------------------------------------------------
__global__ __launch_bounds__(256) void edge_kernel(float* __restrict__ out) {
    const int warp   = (blockIdx.x * blockDim.x + threadIdx.x) >> 5;
    const int lane   = threadIdx.x & 31;
    const int half   = lane >> 4;          // which edge of the pair
    const int sub4   = (lane & 15) * 4;    // 4 halves per lane
    const int nwarps = (gridDim.x * blockDim.x) >> 5;

    for (int e = warp * 2 + half; e < EE; e += nwarps * 2) {
        uint4 rec = g_erec[e];
        const __half* p = g_xw + rec.y + sub4;
        unsigned c = rec.z;

        uint2 Au = *(const uint2*)(p + ((c & 255u) << 6));
        uint2 Bu = *(const uint2*)(p + (((c >> 8) & 255u) << 6));
        uint2 Cu = *(const uint2*)(p + (((c >> 16) & 255u) << 6));
        uint2 Du = *(const uint2*)(p + ((c >> 24) << 6));

        __half2 fh = *(const __half2*)&rec.w;
        float f0 = __low2float(fh), f1 = __high2float(fh);
        float g0 = 1.0f - f0, g1 = 1.0f - f1;
        __half2 w00 = __float2half2_rn(g0 * g1);
        __half2 w10 = __float2half2_rn(f0 * g1);
        __half2 w01 = __float2half2_rn(g0 * f1);
        __half2 w11 = __float2half2_rn(f0 * f1);

        __half2 A0 = *(__half2*)&Au.x, A1 = *(__half2*)&Au.y;
        __half2 B0 = *(__half2*)&Bu.x, B1 = *(__half2*)&Bu.y;
        __half2 C0 = *(__half2*)&Cu.x, C1 = *(__half2*)&Cu.y;
        __half2 D0 = *(__half2*)&Du.x, D1 = *(__half2*)&Du.y;

        __half2 r0 = __hmul2(w00, A0);
        r0 = __hfma2(w10, B0, r0);
        r0 = __hfma2(w01, C0, r0);
        r0 = __hfma2(w11, D0, r0);
        __half2 r1 = __hmul2(w00, A1);
        r1 = __hfma2(w10, B1, r1);
        r1 = __hfma2(w01, C1, r1);
        r1 = __hfma2(w11, D1, r1);

        float2 lo = __half22float2(r0);
        float2 hi = __half22float2(r1);
        float* op = out + rec.x + sub4;
        asm volatile("red.global.add.v4.f32 [%0], {%1, %2, %3, %4};"
                     :: "l"(op), "f"(lo.x), "f"(lo.y), "f"(hi.x), "f"(hi.y)
                     : "memory");
    }
}

// ---------------------------------------------------------------------------
// final (elementwise): out = out/max(deg,1) + xw[n,25,:] + bias
// ---------------------------------------------------------------------------
__global__ __launch_bounds__(256) void final_kernel(const float* __restrict__ bias,
                                                    float* __restrict__ out) {
    int i = blockIdx.x * 256 + threadIdx.x;       // over NN*16 float4-chunks
    if (i >= NN * 16) return;
    int n  = i >> 4;
    int c4 = (i & 15) * 4;
    float scale = 1.0f / fmaxf(g_deg[n], 1.0f);
    float4 o = *(float4*)(out + n * FOUT + c4);
    uint2 hu = *(const uint2*)(g_xw + (size_t)n * KROW + KP * 64 + c4);
    float2 rl = __half22float2(*(__half2*)&hu.x);
    float2 rh = __half22float2(*(__half2*)&hu.y);
    float4 b = *(const float4*)(bias + c4);
    o.x = o.x * scale + rl.x + b.x;
    o.y = o.y * scale + rl.y + b.y;
    o.z = o.z * scale + rh.x + b.z;
    o.w = o.w * scale + rh.y + b.w;
    *(float4*)(out + n * FOUT + c4) = o;
}

// ---------------------------------------------------------------------------
extern "C" void kernel_launch(void* const* d_in, const int* in_sizes, int n_in,
                              void* d_out, int out_size) {
    const float* x      = (const float*)d_in[0];
    const int*   ei     = (const int*)  d_in[1];
    const float* pseudo = (const float*)d_in[2];
    const float* weight = (const float*)d_in[3];
    const float* root   = (const float*)d_in[4];
    const float* bias   = (const float*)d_in[5];
    float* out = (float*)d_out;

    const int smem_bytes = (128 * PADR + 64 * PADR) * (int)sizeof(__half);
    cudaFuncSetAttribute(xw_mma, cudaFuncAttributeMaxDynamicSharedMemorySize, smem_bytes);

    prep_x<<<(NN * 64 + 255) / 256, 256>>>(x, out);
    prep_w<<<(KALL * 64 * 64 + 255) / 256, 256>>>(weight, root);
    hist_kernel<<<(EE + 255) / 256, 256>>>(ei);
    scan_local<<<NBLK, 1024>>>();
    scan_tops<<<1, 64>>>();
    scan_add<<<NBLK, 1024>>>();
    prep_edges<<<(EE + 255) / 256, 256>>>(ei, pseudo);

    dim3 g2((NN + 127) / 128, 6);
    xw_mma<<<g2, 256, smem_bytes>>>();

    edge_kernel<<<6144, 256>>>(out);

    final_kernel<<<(NN * 16 + 255) / 256, 256>>>(bias, out);
}